// round 17
// baseline (speedup 1.0000x reference)
#include <cuda_runtime.h>
#include <math_constants.h>
#include <cstdint>

#define NBATCH    512
#define NTOKS     512
#define DIN       128
#define TOPK_N    12
#define NTHREADS  256

// global scratch (contiguous per tensor for coalesced K2 loads)
__device__ float4 g_k[NBATCH * NTOKS];   // pre-scaled k
__device__ float4 g_q[NBATCH * NTOKS];

// ---------- PTX helpers ----------
__device__ __forceinline__ float ex2f_fast(float x) {
    float r; asm("ex2.approx.f32 %0, %1;" : "=f"(r) : "f"(x)); return r;
}
__device__ __forceinline__ float rcpf_fast(float x) {
    float r; asm("rcp.approx.f32 %0, %1;" : "=f"(r) : "f"(x)); return r;
}
__device__ __forceinline__ unsigned long long pk2(float lo, float hi) {
    unsigned long long r; asm("mov.b64 %0, {%1, %2};" : "=l"(r) : "f"(lo), "f"(hi)); return r;
}
__device__ __forceinline__ void upk2(float& lo, float& hi, unsigned long long v) {
    asm("mov.b64 {%0, %1}, %2;" : "=f"(lo), "=f"(hi) : "l"(v));
}
__device__ __forceinline__ unsigned long long fma2(unsigned long long a,
                                                   unsigned long long b,
                                                   unsigned long long c) {
    unsigned long long r;
    asm("fma.rn.f32x2 %0, %1, %2, %3;" : "=l"(r) : "l"(a), "l"(b), "l"(c));
    return r;
}
__device__ __forceinline__ unsigned long long add2(unsigned long long a,
                                                   unsigned long long b) {
    unsigned long long r;
    asm("add.rn.f32x2 %0, %1, %2;" : "=l"(r) : "l"(a), "l"(b));
    return r;
}
__device__ __forceinline__ void cp_async16(uint32_t saddr, const void* gaddr) {
    asm volatile("cp.async.cg.shared.global [%0], [%1], 16;" :: "r"(saddr), "l"(gaddr));
}
__device__ __forceinline__ unsigned fkey(float v) {
    int b = __float_as_int(v);
    return (unsigned)b ^ (unsigned)((b >> 31) | 0x80000000);
}
// exact-to-2^-26 warp sum of nonneg per-lane partials (each <= ~16).
// REQUIRES dominant partial >= ~2^-26 (guaranteed by true-rowmax shift:
// max arg ~ 0 -> dominant e ~ 1). Two independent REDUX.ADD, no shfl chain.
__device__ __forceinline__ float redux_sum_pos(float partial) {
    unsigned u = __float2uint_rn(partial * 67108864.0f);      // * 2^26, <= 2^30.1
    unsigned losum = __reduce_add_sync(0xffffffffu, u & 0xFFFFu);
    unsigned hisum = __reduce_add_sync(0xffffffffu, u >> 16);
    return fmaf((float)hisum, 65536.0f, (float)losum) * 1.490116119384765625e-8f; // 2^-26
}

// ======================= K1: projection (unchanged, proven) =================
// grid (8, 512) = (chunk of 64 tokens, batch); 256 threads
__global__ __launch_bounds__(NTHREADS)
void proj_kernel(const float* __restrict__ x,
                 const float* __restrict__ wk,
                 const float* __restrict__ wq)
{
    __shared__ float xs[64 * 132];        // 528B token stride, conflict-free
    __shared__ float wks[512], wqs[512];
    __shared__ float4 sc4[128];

    const int tid = threadIdx.x;
    const int c = blockIdx.x;
    const int b = blockIdx.y;
    const float4* xg4 = (const float4*)(x + ((size_t)b * NTOKS + (size_t)c * 64) * DIN);

    for (int i = tid; i < 512; i += NTHREADS) { wks[i] = wk[i]; wqs[i] = wq[i]; }

    uint32_t xs_s = (uint32_t)__cvta_generic_to_shared(xs);
    #pragma unroll
    for (int k2 = 0; k2 < 8; ++k2) {
        int idx = tid + k2 * NTHREADS;          // 0..2047
        int t = idx >> 5, e4 = idx & 31;
        cp_async16(xs_s + (uint32_t)(t * 132 + e4 * 4) * 4u, xg4 + idx);
    }
    asm volatile("cp.async.commit_group;");
    asm volatile("cp.async.wait_group 0;");
    __syncthreads();

    const int token = tid & 63;
    const int dhalf = (tid >> 6) & 1;
    const int proj  = tid >> 7;
    const float4* wsel4 = (const float4*)(proj ? wqs : wks);
    const float4* xr = (const float4*)(xs + token * 132 + dhalf * 64);

    float a0 = 0.f, a1 = 0.f, a2 = 0.f, a3 = 0.f;
    #pragma unroll
    for (int i = 0; i < 16; ++i) {
        float4 xv = xr[i];
        int e4 = dhalf * 16 + i;
        float4 w0 = wsel4[e4 * 4 + 0];
        float4 w1 = wsel4[e4 * 4 + 1];
        float4 w2 = wsel4[e4 * 4 + 2];
        float4 w3 = wsel4[e4 * 4 + 3];
        a0 = fmaf(xv.x, w0.x, a0); a1 = fmaf(xv.x, w0.y, a1);
        a2 = fmaf(xv.x, w0.z, a2); a3 = fmaf(xv.x, w0.w, a3);
        a0 = fmaf(xv.y, w1.x, a0); a1 = fmaf(xv.y, w1.y, a1);
        a2 = fmaf(xv.y, w1.z, a2); a3 = fmaf(xv.y, w1.w, a3);
        a0 = fmaf(xv.z, w2.x, a0); a1 = fmaf(xv.z, w2.y, a1);
        a2 = fmaf(xv.z, w2.z, a2); a3 = fmaf(xv.z, w2.w, a3);
        a0 = fmaf(xv.w, w3.x, a0); a1 = fmaf(xv.w, w3.y, a1);
        a2 = fmaf(xv.w, w3.z, a2); a3 = fmaf(xv.w, w3.w, a3);
    }
    if (dhalf) sc4[proj * 64 + token] = make_float4(a0, a1, a2, a3);
    __syncthreads();
    if (!dhalf) {
        float4 p = sc4[proj * 64 + token];
        a0 += p.x; a1 += p.y; a2 += p.z; a3 += p.w;
        // (1/sqrt(128)) * log2(e) folded into k
        const float KSCALE = 0.0883883476483184405f * 1.4426950408889634074f;
        size_t o = (size_t)b * NTOKS + (size_t)c * 64 + token;
        if (proj == 0)
            g_k[o] = make_float4(a0 * KSCALE, a1 * KSCALE, a2 * KSCALE, a3 * KSCALE);
        else
            g_q[o] = make_float4(a0, a1, a2, a3);
    }
}

// ======================= K2: scores + softmax-sum + topk + gather ===========
// Base = round-10 proven kernel (78us, rel_err 0, 64 regs, no spill).
// Changes (both register-neutral):
//  1. TRUE rowmax via +512 offset: args = l-100 in [-350,+150], so m+512 > 0
//     always -> raw s32 REDUX.MAX on (m+512) is order-exact; -512 after.
//     The +-2^-15 rounding of (m+512)-512 is a shared row shift -> cancels
//     exactly in e/s (softmax shift invariance). args - m <= 2^-15: no inf.
//  2. Fixed-point REDUX warp sum replaces the 5-hop u64 butterfly (~150 ->
//     ~60 serial cyc/pair). Valid because true rowmax makes dominant e ~ 1.
// Cauchy-Schwarz precomputed shifts (R16) are abandoned: slack up to ~200
// log2-units flushes whole rows (dominant included) -> s=0 -> inf poison.
__global__ __launch_bounds__(NTHREADS, 4)
void attn_kernel(const float* __restrict__ x, float* __restrict__ out)
{
    __shared__ float4 ks4[NTOKS];                 // pre-scaled k (8 KB)
    // qp2[pair p][lane]: .x = Q slot 2p, .y = slot 2p+1 (p = 0..15). Lane
    // stride 16B -> 4-phase conflict-free LDS.128 / STS.128. (8 KB)
    __shared__ ulonglong2 qp2[16 * 32];
    __shared__ float Ash[NTOKS];
    __shared__ int sel[16];

    const int tid  = threadIdx.x;
    const int lane = tid & 31;
    const int warp = tid >> 5;
    const int b    = blockIdx.x;
    const float4* kg = g_k + (size_t)b * NTOKS;
    const float4* qg = g_q + (size_t)b * NTOKS;

    // load k (coalesced)
    #pragma unroll
    for (int it = 0; it < 2; ++it) {
        int t = tid + it * NTHREADS;
        ks4[t] = kg[t];
    }
    // load + pack q. Thread (i = tid>>5, ln): lane ln owns cols ln+32j;
    // slot 4i+c packs (col ln+64i, col ln+64i+32) component c.
    {
        int i = tid >> 5, ln = tid & 31;
        int m = ln + 64 * i;
        float4 qa = qg[m];
        float4 qb = qg[m + 32];
        ulonglong2 lo, hi;
        lo.x = pk2(qa.x, qb.x);  lo.y = pk2(qa.y, qb.y);   // slots 4i, 4i+1
        hi.x = pk2(qa.z, qb.z);  hi.y = pk2(qa.w, qb.w);   // slots 4i+2, 4i+3
        qp2[(2 * i) * 32 + ln]     = lo;
        qp2[(2 * i + 1) * 32 + ln] = hi;
    }
    for (int i = tid; i < NTOKS; i += NTHREADS) Ash[i] = 0.f;
    __syncthreads();

    const unsigned long long BIAS = pk2(-100.0f, -100.0f);

    unsigned long long A2[8];
    #pragma unroll
    for (int i = 0; i < 8; ++i) A2[i] = 0ull;

    #pragma unroll 1
    for (int rp = 0; rp < 32; ++rp) {
        int n = warp * 64 + rp * 2;
        float4 ka = ks4[n];
        float4 kb = ks4[n + 1];
        unsigned long long ka0 = pk2(ka.x, ka.x), ka1 = pk2(ka.y, ka.y);
        unsigned long long ka2 = pk2(ka.z, ka.z), ka3 = pk2(ka.w, ka.w);
        unsigned long long kb0 = pk2(kb.x, kb.x), kb1 = pk2(kb.y, kb.y);
        unsigned long long kb2 = pk2(kb.z, kb.z), kb3 = pk2(kb.w, kb.w);

        // dots with -100 bias folded into the accumulator init; Q from smem
        unsigned long long e0[8], e1[8];
        #pragma unroll
        for (int i = 0; i < 8; ++i) {
            ulonglong2 qA = qp2[(2 * i) * 32 + lane];       // slots 4i, 4i+1
            ulonglong2 qB = qp2[(2 * i + 1) * 32 + lane];   // slots 4i+2, 4i+3
            unsigned long long a  = fma2(qA.x, ka0, BIAS);
            unsigned long long bb = fma2(qA.x, kb0, BIAS);
            a  = fma2(qA.y, ka1, a);  bb = fma2(qA.y, kb1, bb);
            a  = fma2(qB.x, ka2, a);  bb = fma2(qB.x, kb2, bb);
            a  = fma2(qB.y, ka3, a);  bb = fma2(qB.y, kb3, bb);
            e0[i] = a; e1[i] = bb;
        }

        // TRUE row max: fmaxf tree, then +512 offset makes all values > 0
        // so raw s32 REDUX.MAX == float max; -512 recovers m (+-2^-15,
        // a shared shift -> exact in the softmax ratio).
        float m0 = -CUDART_INF_F, m1 = -CUDART_INF_F;
        #pragma unroll
        for (int i = 0; i < 8; ++i) {
            float lo, hi;
            upk2(lo, hi, e0[i]); m0 = fmaxf(m0, fmaxf(lo, hi));
            upk2(lo, hi, e1[i]); m1 = fmaxf(m1, fmaxf(lo, hi));
        }
        m0 = __int_as_float(__reduce_max_sync(0xffffffffu,
                 __float_as_int(m0 + 512.0f))) - 512.0f;
        m1 = __int_as_float(__reduce_max_sync(0xffffffffu,
                 __float_as_int(m1 + 512.0f))) - 512.0f;

        // subtract shift (packed), exp2: args <= ~0 -> e <= ~1 always
        unsigned long long S0 = pk2(-m0, -m0), S1 = pk2(-m1, -m1);
        #pragma unroll
        for (int i = 0; i < 8; ++i) {
            float lo, hi;
            upk2(lo, hi, add2(e0[i], S0));
            e0[i] = pk2(ex2f_fast(lo), ex2f_fast(hi));
            upk2(lo, hi, add2(e1[i], S1));
            e1[i] = pk2(ex2f_fast(lo), ex2f_fast(hi));
        }

        // packed lane-sum trees, then shfl-free fixed-point REDUX warp sum
        // (valid: true rowmax -> dominant e ~ 1 -> s >= ~1)
        unsigned long long t0 = add2(add2(add2(e0[0], e0[1]), add2(e0[2], e0[3])),
                                     add2(add2(e0[4], e0[5]), add2(e0[6], e0[7])));
        unsigned long long t1 = add2(add2(add2(e1[0], e1[1]), add2(e1[2], e1[3])),
                                     add2(add2(e1[4], e1[5]), add2(e1[6], e1[7])));
        float lo, hi;
        upk2(lo, hi, t0); float s0 = lo + hi;
        upk2(lo, hi, t1); float s1 = lo + hi;
        s0 = redux_sum_pos(s0);
        s1 = redux_sum_pos(s1);

        unsigned long long v0, v1;
        {
            float i0 = rcpf_fast(s0), i1 = rcpf_fast(s1);
            v0 = pk2(i0, i0); v1 = pk2(i1, i1);
        }
        #pragma unroll
        for (int i = 0; i < 8; ++i) {
            A2[i] = fma2(e0[i], v0, A2[i]);
            A2[i] = fma2(e1[i], v1, A2[i]);
        }
    }

    #pragma unroll
    for (int i = 0; i < 8; ++i) {
        float lo, hi;
        upk2(lo, hi, A2[i]);
        atomicAdd(&Ash[lane + 64 * i], lo);
        atomicAdd(&Ash[lane + 64 * i + 32], hi);
    }
    __syncthreads();

    // top-12: JAX order (descending, ties -> lower index)
    if (warp == 0) {
        float av[16];
        #pragma unroll
        for (int j = 0; j < 16; ++j) av[j] = Ash[lane + 32 * j];
        #pragma unroll 1
        for (int t = 0; t < TOPK_N; ++t) {
            float bv = -CUDART_INF_F;
            int   bi = 0x7fffffff;
            #pragma unroll
            for (int j = 0; j < 16; ++j) {
                float v = av[j];
                if (v > bv) { bv = v; bi = lane + 32 * j; }
            }
            unsigned key = fkey(bv);
            unsigned win = __reduce_max_sync(0xffffffffu, key);
            unsigned cand = (key == win) ? (unsigned)bi : 0x7fffffffu;
            int idx = (int)__reduce_min_sync(0xffffffffu, cand);
            if (lane == 0) sel[t] = idx;
            #pragma unroll
            for (int j = 0; j < 16; ++j)
                if (idx == lane + 32 * j) av[j] = -CUDART_INF_F;
        }
    }
    __syncthreads();

    const float4* xb4 = (const float4*)(x + (size_t)b * NTOKS * DIN);
    float4* ob4 = (float4*)(out + (size_t)b * TOPK_N * DIN);
    for (int i = tid; i < TOPK_N * 32; i += NTHREADS) {
        int t  = i >> 5;
        int e4 = i & 31;
        ob4[i] = xb4[sel[t] * 32 + e4];
    }
}

extern "C" void kernel_launch(void* const* d_in, const int* in_sizes, int n_in,
                              void* d_out, int out_size)
{
    const float* x  = (const float*)d_in[0];
    const float* wk = (const float*)d_in[1];
    const float* wq = (const float*)d_in[2];
    float* out = (float*)d_out;
    (void)in_sizes; (void)n_in; (void)out_size;

    dim3 g1(8, NBATCH);
    proj_kernel<<<g1, NTHREADS>>>(x, wk, wq);
    attn_kernel<<<NBATCH, NTHREADS>>>(x, out);
}